// round 1
// baseline (speedup 1.0000x reference)
#include <cuda_runtime.h>
#include <cstdint>

#define NMAX 100000
#define HID  128

// Scratch (static device globals — allocation-free per harness rules)
__device__ float g_norm[NMAX];
__device__ float g_t1[(size_t)NMAX * HID];
__device__ float g_t2[(size_t)NMAX * HID];
__device__ float g_h1[(size_t)NMAX * HID];
__device__ float g_h2[(size_t)NMAX * HID];

// ---------------------------------------------------------------------------
// degree + norm
// ---------------------------------------------------------------------------
__global__ void deg_kernel(const int* __restrict__ dst, int E, float* __restrict__ norm) {
    int i = blockIdx.x * blockDim.x + threadIdx.x;
    if (i < E) atomicAdd(&norm[dst[i]], 1.0f);
}

__global__ void norm_kernel(float* __restrict__ norm, int N) {
    int i = blockIdx.x * blockDim.x + threadIdx.x;
    if (i < N) norm[i] = rsqrtf(fmaxf(norm[i], 1.0f));
}

// ---------------------------------------------------------------------------
// propagation: out[dst] += h[src] * norm[src] * norm[dst]   (vector red, f32x4)
// ---------------------------------------------------------------------------
__device__ __forceinline__ void red4(float* p, float4 v) {
    asm volatile("red.global.add.v4.f32 [%0], {%1,%2,%3,%4};"
                 :: "l"(p), "f"(v.x), "f"(v.y), "f"(v.z), "f"(v.w) : "memory");
}

template <int D>
__global__ void prop_kernel(const float* __restrict__ h, const float* __restrict__ norm,
                            const int* __restrict__ src, const int* __restrict__ dst,
                            float* __restrict__ out, int E) {
    constexpr int G = D / 4;                     // threads per edge
    int t = blockIdx.x * blockDim.x + threadIdx.x;
    int e = t / G;
    int lane = t & (G - 1);
    if (e >= E) return;
    int s = __ldg(src + e);
    int d = __ldg(dst + e);
    float sc = __ldg(norm + s) * __ldg(norm + d);
    float4 v = __ldg(reinterpret_cast<const float4*>(h + (size_t)s * D) + lane);
    v.x *= sc; v.y *= sc; v.z *= sc; v.w *= sc;
    red4(reinterpret_cast<float*>(reinterpret_cast<float4*>(out + (size_t)d * D) + lane), v);
}

// ---------------------------------------------------------------------------
// fused GEMM: out = relu(H0@W[0:DIN] + H1@W[DIN:2DIN] + H2@W[2DIN:3DIN] + b)
// W is [(3*DIN), 128] row-major. BM=128, BN=128, BK=16, 256 threads, 8x8 microtile.
// ---------------------------------------------------------------------------
template <int DIN>
__global__ __launch_bounds__(256)
void gemm3_relu(const float* __restrict__ H0, const float* __restrict__ H1,
                const float* __restrict__ H2, const float* __restrict__ W,
                const float* __restrict__ bias, float* __restrict__ out, int N) {
    __shared__ float As[16][128 + 4];   // transposed A tile: As[k][m]
    __shared__ float Bs[16][128];

    const int tid = threadIdx.x;
    const int m0  = blockIdx.x * 128;
    const int tm  = (tid >> 4) * 8;
    const int tn  = (tid & 15) * 8;

    float c[8][8];
#pragma unroll
    for (int i = 0; i < 8; i++)
#pragma unroll
        for (int j = 0; j < 8; j++) c[i][j] = 0.0f;

    const float* srcs[3] = {H0, H1, H2};

    const int aRow = tid >> 2;          // 0..63
    const int aCol = (tid & 3) * 4;     // 0,4,8,12
    const int bRow = tid >> 5;          // 0..7
    const int bCol = (tid & 31) * 4;    // 0..124

    for (int part = 0; part < 3; ++part) {
        const float* __restrict__ Hp = srcs[part];
        for (int k0 = 0; k0 < DIN; k0 += 16) {
            // load A tile (128 rows x 16 k), store transposed
#pragma unroll
            for (int r = 0; r < 128; r += 64) {
                int row = m0 + aRow + r;
                float4 v = make_float4(0.f, 0.f, 0.f, 0.f);
                if (row < N)
                    v = __ldg(reinterpret_cast<const float4*>(Hp + (size_t)row * DIN + k0 + aCol));
                As[aCol + 0][aRow + r] = v.x;
                As[aCol + 1][aRow + r] = v.y;
                As[aCol + 2][aRow + r] = v.z;
                As[aCol + 3][aRow + r] = v.w;
            }
            // load B tile (16 k-rows x 128 n)
#pragma unroll
            for (int r = 0; r < 16; r += 8) {
                float4 v = __ldg(reinterpret_cast<const float4*>(
                    W + (size_t)(part * DIN + k0 + bRow + r) * 128 + bCol));
                *reinterpret_cast<float4*>(&Bs[bRow + r][bCol]) = v;
            }
            __syncthreads();

#pragma unroll
            for (int kk = 0; kk < 16; ++kk) {
                float rA[8], rB[8];
#pragma unroll
                for (int i = 0; i < 8; i++) rA[i] = As[kk][tm + i];
#pragma unroll
                for (int j = 0; j < 8; j++) rB[j] = Bs[kk][tn + j];
#pragma unroll
                for (int i = 0; i < 8; i++)
#pragma unroll
                    for (int j = 0; j < 8; j++) c[i][j] += rA[i] * rB[j];
            }
            __syncthreads();
        }
    }

    float bv[8];
#pragma unroll
    for (int j = 0; j < 8; j++) bv[j] = __ldg(bias + tn + j);

#pragma unroll
    for (int i = 0; i < 8; i++) {
        int row = m0 + tm + i;
        if (row < N) {
            float4 o0, o1;
            o0.x = fmaxf(c[i][0] + bv[0], 0.f);
            o0.y = fmaxf(c[i][1] + bv[1], 0.f);
            o0.z = fmaxf(c[i][2] + bv[2], 0.f);
            o0.w = fmaxf(c[i][3] + bv[3], 0.f);
            o1.x = fmaxf(c[i][4] + bv[4], 0.f);
            o1.y = fmaxf(c[i][5] + bv[5], 0.f);
            o1.z = fmaxf(c[i][6] + bv[6], 0.f);
            o1.w = fmaxf(c[i][7] + bv[7], 0.f);
            float* op = out + (size_t)row * 128 + tn;
            *reinterpret_cast<float4*>(op)     = o0;
            *reinterpret_cast<float4*>(op + 4) = o1;
        }
    }
}

// ---------------------------------------------------------------------------
// launch
// ---------------------------------------------------------------------------
extern "C" void kernel_launch(void* const* d_in, const int* in_sizes, int n_in,
                              void* d_out, int out_size) {
    const float* x   = (const float*)d_in[0];
    const int*   src = (const int*)d_in[1];
    const int*   dst = (const int*)d_in[2];
    const float* W1  = (const float*)d_in[3];
    const float* b1  = (const float*)d_in[4];
    const float* W2  = (const float*)d_in[5];
    const float* b2  = (const float*)d_in[6];
    const float* W3  = (const float*)d_in[7];
    const float* b3  = (const float*)d_in[8];
    float* out = (float*)d_out;

    const int N = in_sizes[0] / 32;
    const int E = in_sizes[1];

    float *p_norm, *p_t1, *p_t2, *p_h1, *p_h2;
    cudaGetSymbolAddress((void**)&p_norm, g_norm);
    cudaGetSymbolAddress((void**)&p_t1,   g_t1);
    cudaGetSymbolAddress((void**)&p_t2,   g_t2);
    cudaGetSymbolAddress((void**)&p_h1,   g_h1);
    cudaGetSymbolAddress((void**)&p_h2,   g_h2);

    const int TB = 256;

    // degree + norm
    cudaMemsetAsync(p_norm, 0, (size_t)N * sizeof(float));
    deg_kernel<<<(E + TB - 1) / TB, TB>>>(dst, E, p_norm);
    norm_kernel<<<(N + TB - 1) / TB, TB>>>(p_norm, N);

    // ---- layer 1 (din = 32) ----
    {
        const long long work = (long long)E * 8;   // G = 8
        cudaMemsetAsync(p_t1, 0, (size_t)N * 32 * sizeof(float));
        prop_kernel<32><<<(int)((work + TB - 1) / TB), TB>>>(x, p_norm, src, dst, p_t1, E);
        cudaMemsetAsync(p_t2, 0, (size_t)N * 32 * sizeof(float));
        prop_kernel<32><<<(int)((work + TB - 1) / TB), TB>>>(p_t1, p_norm, src, dst, p_t2, E);
        gemm3_relu<32><<<(N + 127) / 128, 256>>>(x, p_t1, p_t2, W1, b1, p_h1, N);
    }

    // ---- layer 2 (din = 128) ----
    {
        const long long work = (long long)E * 32;  // G = 32
        cudaMemsetAsync(p_t1, 0, (size_t)N * 128 * sizeof(float));
        prop_kernel<128><<<(int)((work + TB - 1) / TB), TB>>>(p_h1, p_norm, src, dst, p_t1, E);
        cudaMemsetAsync(p_t2, 0, (size_t)N * 128 * sizeof(float));
        prop_kernel<128><<<(int)((work + TB - 1) / TB), TB>>>(p_t1, p_norm, src, dst, p_t2, E);
        gemm3_relu<128><<<(N + 127) / 128, 256>>>(p_h1, p_t1, p_t2, W2, b2, p_h2, N);
    }

    // ---- layer 3 (din = 128) ----
    {
        const long long work = (long long)E * 32;
        cudaMemsetAsync(p_t1, 0, (size_t)N * 128 * sizeof(float));
        prop_kernel<128><<<(int)((work + TB - 1) / TB), TB>>>(p_h2, p_norm, src, dst, p_t1, E);
        cudaMemsetAsync(p_t2, 0, (size_t)N * 128 * sizeof(float));
        prop_kernel<128><<<(int)((work + TB - 1) / TB), TB>>>(p_t1, p_norm, src, dst, p_t2, E);
        gemm3_relu<128><<<(N + 127) / 128, 256>>>(p_h2, p_t1, p_t2, W3, b3, out, N);
    }
}

// round 2
// speedup vs baseline: 1.7444x; 1.7444x over previous
#include <cuda_runtime.h>
#include <cstdint>

#define NMAX 100000
#define EMAX 1600000
#define HID  128

// Scratch (static device globals — allocation-free per harness rules)
__device__ float g_norm[NMAX];
__device__ int   g_cnt[NMAX];
__device__ int   g_rowptr[NMAX + 1];
__device__ int   g_cursor[NMAX];
__device__ int   g_bsums[128];
__device__ int   g_csr[EMAX];
__device__ float g_t1[(size_t)NMAX * HID];
__device__ float g_t2[(size_t)NMAX * HID];
__device__ float g_h1[(size_t)NMAX * HID];
__device__ float g_h2[(size_t)NMAX * HID];

// ---------------------------------------------------------------------------
// degree histogram + norm
// ---------------------------------------------------------------------------
__global__ void hist_kernel(const int* __restrict__ dst, int E, int* __restrict__ cnt) {
    int i = blockIdx.x * blockDim.x + threadIdx.x;
    if (i < E) atomicAdd(&cnt[dst[i]], 1);
}

__global__ void norm_kernel(const int* __restrict__ cnt, float* __restrict__ norm, int N) {
    int i = blockIdx.x * blockDim.x + threadIdx.x;
    if (i < N) norm[i] = rsqrtf(fmaxf((float)cnt[i], 1.0f));
}

// ---------------------------------------------------------------------------
// exclusive scan of cnt -> rowptr  (1024 elems/block, 256 threads x 4)
// ---------------------------------------------------------------------------
__global__ void scan_block(const int* __restrict__ cnt, int* __restrict__ out,
                           int* __restrict__ bsums, int N) {
    __shared__ int ss[256];
    const int tid  = threadIdx.x;
    const int base = blockIdx.x * 1024 + tid * 4;
    int local[4];
#pragma unroll
    for (int i = 0; i < 4; i++) {
        int g = base + i;
        local[i] = (g < N) ? cnt[g] : 0;
    }
    int tsum = local[0] + local[1] + local[2] + local[3];
    ss[tid] = tsum;
    __syncthreads();
#pragma unroll
    for (int off = 1; off < 256; off <<= 1) {
        int v = (tid >= off) ? ss[tid - off] : 0;
        __syncthreads();
        ss[tid] += v;
        __syncthreads();
    }
    int run = ss[tid] - tsum;   // exclusive
#pragma unroll
    for (int i = 0; i < 4; i++) {
        int g = base + i;
        if (g < N) out[g] = run;
        run += local[i];
    }
    if (tid == 255) bsums[blockIdx.x] = ss[255];
}

__global__ void scan_sums(int* __restrict__ bsums, int nb) {
    __shared__ int ss[128];
    int tid = threadIdx.x;
    int v = (tid < nb) ? bsums[tid] : 0;
    ss[tid] = v;
    __syncthreads();
#pragma unroll
    for (int off = 1; off < 128; off <<= 1) {
        int u = (tid >= off) ? ss[tid - off] : 0;
        __syncthreads();
        ss[tid] += u;
        __syncthreads();
    }
    if (tid < nb) bsums[tid] = ss[tid] - v;   // exclusive
}

__global__ void add_off(int* __restrict__ out, const int* __restrict__ bsums,
                        int N, int E) {
    int g = blockIdx.x * 1024 + threadIdx.x * 4;
    int o = bsums[blockIdx.x];
#pragma unroll
    for (int i = 0; i < 4; i++)
        if (g + i < N) out[g + i] += o;
    if (blockIdx.x == 0 && threadIdx.x == 0) out[N] = E;
}

__global__ void scatter_kernel(const int* __restrict__ src, const int* __restrict__ dst,
                               int E, int* __restrict__ cursor, int* __restrict__ csr) {
    int e = blockIdx.x * blockDim.x + threadIdx.x;
    if (e < E) {
        int d = dst[e];
        int pos = atomicAdd(&cursor[d], 1);
        csr[pos] = src[e];
    }
}

// ---------------------------------------------------------------------------
// pull propagation: out[d] = norm[d] * sum_{s in row(d)} norm[s]*h[s]
// D=128: one warp per node (32 lanes x float4)
// ---------------------------------------------------------------------------
__global__ __launch_bounds__(256)
void prop_pull128(const float* __restrict__ h, const float* __restrict__ norm,
                  const int* __restrict__ rowptr, const int* __restrict__ csr,
                  float* __restrict__ out, int N) {
    int warp = (blockIdx.x * blockDim.x + threadIdx.x) >> 5;
    int lane = threadIdx.x & 31;
    if (warp >= N) return;
    int beg = __ldg(rowptr + warp), end = __ldg(rowptr + warp + 1);
    const float4* __restrict__ h4 = reinterpret_cast<const float4*>(h);
    float4 acc = make_float4(0.f, 0.f, 0.f, 0.f);
    int e = beg;
    for (; e + 4 <= end; e += 4) {
        int s0 = __ldg(csr + e), s1 = __ldg(csr + e + 1);
        int s2 = __ldg(csr + e + 2), s3 = __ldg(csr + e + 3);
        float n0 = __ldg(norm + s0), n1 = __ldg(norm + s1);
        float n2 = __ldg(norm + s2), n3 = __ldg(norm + s3);
        float4 v0 = __ldg(h4 + (size_t)s0 * 32 + lane);
        float4 v1 = __ldg(h4 + (size_t)s1 * 32 + lane);
        float4 v2 = __ldg(h4 + (size_t)s2 * 32 + lane);
        float4 v3 = __ldg(h4 + (size_t)s3 * 32 + lane);
        acc.x += v0.x * n0 + v1.x * n1 + v2.x * n2 + v3.x * n3;
        acc.y += v0.y * n0 + v1.y * n1 + v2.y * n2 + v3.y * n3;
        acc.z += v0.z * n0 + v1.z * n1 + v2.z * n2 + v3.z * n3;
        acc.w += v0.w * n0 + v1.w * n1 + v2.w * n2 + v3.w * n3;
    }
    for (; e < end; ++e) {
        int s = __ldg(csr + e);
        float n = __ldg(norm + s);
        float4 v = __ldg(h4 + (size_t)s * 32 + lane);
        acc.x += v.x * n; acc.y += v.y * n; acc.z += v.z * n; acc.w += v.w * n;
    }
    float nd = __ldg(norm + warp);
    acc.x *= nd; acc.y *= nd; acc.z *= nd; acc.w *= nd;
    reinterpret_cast<float4*>(out)[(size_t)warp * 32 + lane] = acc;
}

// D=32: 8 lanes per node
__global__ __launch_bounds__(256)
void prop_pull32(const float* __restrict__ h, const float* __restrict__ norm,
                 const int* __restrict__ rowptr, const int* __restrict__ csr,
                 float* __restrict__ out, int N) {
    int t = blockIdx.x * blockDim.x + threadIdx.x;
    int node = t >> 3;
    int lane = t & 7;
    if (node >= N) return;
    int beg = __ldg(rowptr + node), end = __ldg(rowptr + node + 1);
    const float4* __restrict__ h4 = reinterpret_cast<const float4*>(h);
    float4 acc = make_float4(0.f, 0.f, 0.f, 0.f);
    int e = beg;
    for (; e + 4 <= end; e += 4) {
        int s0 = __ldg(csr + e), s1 = __ldg(csr + e + 1);
        int s2 = __ldg(csr + e + 2), s3 = __ldg(csr + e + 3);
        float n0 = __ldg(norm + s0), n1 = __ldg(norm + s1);
        float n2 = __ldg(norm + s2), n3 = __ldg(norm + s3);
        float4 v0 = __ldg(h4 + (size_t)s0 * 8 + lane);
        float4 v1 = __ldg(h4 + (size_t)s1 * 8 + lane);
        float4 v2 = __ldg(h4 + (size_t)s2 * 8 + lane);
        float4 v3 = __ldg(h4 + (size_t)s3 * 8 + lane);
        acc.x += v0.x * n0 + v1.x * n1 + v2.x * n2 + v3.x * n3;
        acc.y += v0.y * n0 + v1.y * n1 + v2.y * n2 + v3.y * n3;
        acc.z += v0.z * n0 + v1.z * n1 + v2.z * n2 + v3.z * n3;
        acc.w += v0.w * n0 + v1.w * n1 + v2.w * n2 + v3.w * n3;
    }
    for (; e < end; ++e) {
        int s = __ldg(csr + e);
        float n = __ldg(norm + s);
        float4 v = __ldg(h4 + (size_t)s * 8 + lane);
        acc.x += v.x * n; acc.y += v.y * n; acc.z += v.z * n; acc.w += v.w * n;
    }
    float nd = __ldg(norm + node);
    acc.x *= nd; acc.y *= nd; acc.z *= nd; acc.w *= nd;
    reinterpret_cast<float4*>(out)[(size_t)node * 8 + lane] = acc;
}

// ---------------------------------------------------------------------------
// fused GEMM: out = relu(H0@W[0:DIN] + H1@W[DIN:2DIN] + H2@W[2DIN:3DIN] + b)
// ---------------------------------------------------------------------------
template <int DIN>
__global__ __launch_bounds__(256)
void gemm3_relu(const float* __restrict__ H0, const float* __restrict__ H1,
                const float* __restrict__ H2, const float* __restrict__ W,
                const float* __restrict__ bias, float* __restrict__ out, int N) {
    __shared__ __align__(16) float As[16][132];   // transposed A tile: As[k][m]
    __shared__ __align__(16) float Bs[16][128];

    const int tid = threadIdx.x;
    const int m0  = blockIdx.x * 128;
    const int tm  = (tid >> 4) * 8;
    const int tn  = (tid & 15) * 8;

    float c[8][8];
#pragma unroll
    for (int i = 0; i < 8; i++)
#pragma unroll
        for (int j = 0; j < 8; j++) c[i][j] = 0.0f;

    const float* srcs[3] = {H0, H1, H2};

    const int aRow = tid >> 2;          // 0..63
    const int aCol = (tid & 3) * 4;     // 0,4,8,12
    const int bRow = tid >> 5;          // 0..7
    const int bCol = (tid & 31) * 4;    // 0..124

    for (int part = 0; part < 3; ++part) {
        const float* __restrict__ Hp = srcs[part];
        for (int k0 = 0; k0 < DIN; k0 += 16) {
#pragma unroll
            for (int r = 0; r < 128; r += 64) {
                int row = m0 + aRow + r;
                float4 v = make_float4(0.f, 0.f, 0.f, 0.f);
                if (row < N)
                    v = __ldg(reinterpret_cast<const float4*>(Hp + (size_t)row * DIN + k0 + aCol));
                As[aCol + 0][aRow + r] = v.x;
                As[aCol + 1][aRow + r] = v.y;
                As[aCol + 2][aRow + r] = v.z;
                As[aCol + 3][aRow + r] = v.w;
            }
#pragma unroll
            for (int r = 0; r < 16; r += 8) {
                float4 v = __ldg(reinterpret_cast<const float4*>(
                    W + (size_t)(part * DIN + k0 + bRow + r) * 128 + bCol));
                *reinterpret_cast<float4*>(&Bs[bRow + r][bCol]) = v;
            }
            __syncthreads();

#pragma unroll
            for (int kk = 0; kk < 16; ++kk) {
                float4 a0 = *reinterpret_cast<const float4*>(&As[kk][tm]);
                float4 a1 = *reinterpret_cast<const float4*>(&As[kk][tm + 4]);
                float4 b0 = *reinterpret_cast<const float4*>(&Bs[kk][tn]);
                float4 b1 = *reinterpret_cast<const float4*>(&Bs[kk][tn + 4]);
                float rA[8] = {a0.x, a0.y, a0.z, a0.w, a1.x, a1.y, a1.z, a1.w};
                float rB[8] = {b0.x, b0.y, b0.z, b0.w, b1.x, b1.y, b1.z, b1.w};
#pragma unroll
                for (int i = 0; i < 8; i++)
#pragma unroll
                    for (int j = 0; j < 8; j++) c[i][j] += rA[i] * rB[j];
            }
            __syncthreads();
        }
    }

    float bv[8];
#pragma unroll
    for (int j = 0; j < 8; j++) bv[j] = __ldg(bias + tn + j);

#pragma unroll
    for (int i = 0; i < 8; i++) {
        int row = m0 + tm + i;
        if (row < N) {
            float4 o0, o1;
            o0.x = fmaxf(c[i][0] + bv[0], 0.f);
            o0.y = fmaxf(c[i][1] + bv[1], 0.f);
            o0.z = fmaxf(c[i][2] + bv[2], 0.f);
            o0.w = fmaxf(c[i][3] + bv[3], 0.f);
            o1.x = fmaxf(c[i][4] + bv[4], 0.f);
            o1.y = fmaxf(c[i][5] + bv[5], 0.f);
            o1.z = fmaxf(c[i][6] + bv[6], 0.f);
            o1.w = fmaxf(c[i][7] + bv[7], 0.f);
            float* op = out + (size_t)row * 128 + tn;
            *reinterpret_cast<float4*>(op)     = o0;
            *reinterpret_cast<float4*>(op + 4) = o1;
        }
    }
}

// ---------------------------------------------------------------------------
// launch
// ---------------------------------------------------------------------------
extern "C" void kernel_launch(void* const* d_in, const int* in_sizes, int n_in,
                              void* d_out, int out_size) {
    const float* x   = (const float*)d_in[0];
    const int*   src = (const int*)d_in[1];
    const int*   dst = (const int*)d_in[2];
    const float* W1  = (const float*)d_in[3];
    const float* b1  = (const float*)d_in[4];
    const float* W2  = (const float*)d_in[5];
    const float* b2  = (const float*)d_in[6];
    const float* W3  = (const float*)d_in[7];
    const float* b3  = (const float*)d_in[8];
    float* out = (float*)d_out;

    const int N = in_sizes[0] / 32;
    const int E = in_sizes[1];

    float *p_norm, *p_t1, *p_t2, *p_h1, *p_h2;
    int *p_cnt, *p_rowptr, *p_cursor, *p_bsums, *p_csr;
    cudaGetSymbolAddress((void**)&p_norm,   g_norm);
    cudaGetSymbolAddress((void**)&p_cnt,    g_cnt);
    cudaGetSymbolAddress((void**)&p_rowptr, g_rowptr);
    cudaGetSymbolAddress((void**)&p_cursor, g_cursor);
    cudaGetSymbolAddress((void**)&p_bsums,  g_bsums);
    cudaGetSymbolAddress((void**)&p_csr,    g_csr);
    cudaGetSymbolAddress((void**)&p_t1,     g_t1);
    cudaGetSymbolAddress((void**)&p_t2,     g_t2);
    cudaGetSymbolAddress((void**)&p_h1,     g_h1);
    cudaGetSymbolAddress((void**)&p_h2,     g_h2);

    const int TB = 256;
    const int nb = (N + 1023) / 1024;

    // degree + norm
    cudaMemsetAsync(p_cnt, 0, (size_t)N * sizeof(int));
    hist_kernel<<<(E + TB - 1) / TB, TB>>>(dst, E, p_cnt);
    norm_kernel<<<(N + TB - 1) / TB, TB>>>(p_cnt, p_norm, N);

    // CSR build
    scan_block<<<nb, 256>>>(p_cnt, p_rowptr, p_bsums, N);
    scan_sums<<<1, 128>>>(p_bsums, nb);
    add_off<<<nb, 256>>>(p_rowptr, p_bsums, N, E);
    cudaMemcpyAsync(p_cursor, p_rowptr, (size_t)N * sizeof(int),
                    cudaMemcpyDeviceToDevice);
    scatter_kernel<<<(E + TB - 1) / TB, TB>>>(src, dst, E, p_cursor, p_csr);

    const int g128 = (N * 32 + TB - 1) / TB;   // warp per node
    const int g32  = (N * 8 + TB - 1) / TB;    // 8 lanes per node

    // ---- layer 1 (din = 32) ----
    prop_pull32<<<g32, TB>>>(x,    p_norm, p_rowptr, p_csr, p_t1, N);
    prop_pull32<<<g32, TB>>>(p_t1, p_norm, p_rowptr, p_csr, p_t2, N);
    gemm3_relu<32><<<(N + 127) / 128, 256>>>(x, p_t1, p_t2, W1, b1, p_h1, N);

    // ---- layer 2 (din = 128) ----
    prop_pull128<<<g128, TB>>>(p_h1, p_norm, p_rowptr, p_csr, p_t1, N);
    prop_pull128<<<g128, TB>>>(p_t1, p_norm, p_rowptr, p_csr, p_t2, N);
    gemm3_relu<128><<<(N + 127) / 128, 256>>>(p_h1, p_t1, p_t2, W2, b2, p_h2, N);

    // ---- layer 3 (din = 128) ----
    prop_pull128<<<g128, TB>>>(p_h2, p_norm, p_rowptr, p_csr, p_t1, N);
    prop_pull128<<<g128, TB>>>(p_t1, p_norm, p_rowptr, p_csr, p_t2, N);
    gemm3_relu<128><<<(N + 127) / 128, 256>>>(p_h2, p_t1, p_t2, W3, b3, out, N);
}

// round 4
// speedup vs baseline: 2.3290x; 1.3351x over previous
#include <cuda_runtime.h>
#include <cstdint>

#define NMAX 100000
#define EMAX 1600000
#define HID  128

// Scratch (static device globals — allocation-free per harness rules)
__device__ float g_norm[NMAX];
__device__ int   g_cnt[NMAX];
__device__ int   g_rowptr[NMAX + 1];
__device__ int   g_cursor[NMAX];
__device__ int   g_bsums[128];
__device__ int   g_csr[EMAX];
__device__ float g_t1[(size_t)NMAX * HID];
__device__ float g_t2[(size_t)NMAX * HID];
__device__ float g_h1[(size_t)NMAX * HID];
__device__ float g_h2[(size_t)NMAX * HID];

// ---------------------------------------------------------------------------
// degree histogram + norm
// ---------------------------------------------------------------------------
__global__ void hist_kernel(const int* __restrict__ dst, int E, int* __restrict__ cnt) {
    int i = blockIdx.x * blockDim.x + threadIdx.x;
    if (i < E) atomicAdd(&cnt[dst[i]], 1);
}

__global__ void norm_kernel(const int* __restrict__ cnt, float* __restrict__ norm, int N) {
    int i = blockIdx.x * blockDim.x + threadIdx.x;
    if (i < N) norm[i] = rsqrtf(fmaxf((float)cnt[i], 1.0f));
}

// ---------------------------------------------------------------------------
// exclusive scan of cnt -> rowptr  (1024 elems/block, 256 threads x 4)
// ---------------------------------------------------------------------------
__global__ void scan_block(const int* __restrict__ cnt, int* __restrict__ out,
                           int* __restrict__ bsums, int N) {
    __shared__ int ss[256];
    const int tid  = threadIdx.x;
    const int base = blockIdx.x * 1024 + tid * 4;
    int local[4];
#pragma unroll
    for (int i = 0; i < 4; i++) {
        int g = base + i;
        local[i] = (g < N) ? cnt[g] : 0;
    }
    int tsum = local[0] + local[1] + local[2] + local[3];
    ss[tid] = tsum;
    __syncthreads();
#pragma unroll
    for (int off = 1; off < 256; off <<= 1) {
        int v = (tid >= off) ? ss[tid - off] : 0;
        __syncthreads();
        ss[tid] += v;
        __syncthreads();
    }
    int run = ss[tid] - tsum;   // exclusive
#pragma unroll
    for (int i = 0; i < 4; i++) {
        int g = base + i;
        if (g < N) out[g] = run;
        run += local[i];
    }
    if (tid == 255) bsums[blockIdx.x] = ss[255];
}

__global__ void scan_sums(int* __restrict__ bsums, int nb) {
    __shared__ int ss[128];
    int tid = threadIdx.x;
    int v = (tid < nb) ? bsums[tid] : 0;
    ss[tid] = v;
    __syncthreads();
#pragma unroll
    for (int off = 1; off < 128; off <<= 1) {
        int u = (tid >= off) ? ss[tid - off] : 0;
        __syncthreads();
        ss[tid] += u;
        __syncthreads();
    }
    if (tid < nb) bsums[tid] = ss[tid] - v;   // exclusive
}

__global__ void add_off(int* __restrict__ out, const int* __restrict__ bsums,
                        int N, int E) {
    int g = blockIdx.x * 1024 + threadIdx.x * 4;
    int o = bsums[blockIdx.x];
#pragma unroll
    for (int i = 0; i < 4; i++)
        if (g + i < N) out[g + i] += o;
    if (blockIdx.x == 0 && threadIdx.x == 0) out[N] = E;
}

__global__ void scatter_kernel(const int* __restrict__ src, const int* __restrict__ dst,
                               int E, int* __restrict__ cursor, int* __restrict__ csr) {
    int e = blockIdx.x * blockDim.x + threadIdx.x;
    if (e < E) {
        int d = dst[e];
        int pos = atomicAdd(&cursor[d], 1);
        csr[pos] = src[e];
    }
}

// ---------------------------------------------------------------------------
// pull propagation: out[d] = norm[d] * sum_{s in row(d)} norm[s]*h[s]
// ---------------------------------------------------------------------------
__global__ __launch_bounds__(256)
void prop_pull128(const float* __restrict__ h, const float* __restrict__ norm,
                  const int* __restrict__ rowptr, const int* __restrict__ csr,
                  float* __restrict__ out, int N) {
    int warp = (blockIdx.x * blockDim.x + threadIdx.x) >> 5;
    int lane = threadIdx.x & 31;
    if (warp >= N) return;
    int beg = __ldg(rowptr + warp), end = __ldg(rowptr + warp + 1);
    const float4* __restrict__ h4 = reinterpret_cast<const float4*>(h);
    float4 acc = make_float4(0.f, 0.f, 0.f, 0.f);
    int e = beg;
    for (; e + 4 <= end; e += 4) {
        int s0 = __ldg(csr + e), s1 = __ldg(csr + e + 1);
        int s2 = __ldg(csr + e + 2), s3 = __ldg(csr + e + 3);
        float n0 = __ldg(norm + s0), n1 = __ldg(norm + s1);
        float n2 = __ldg(norm + s2), n3 = __ldg(norm + s3);
        float4 v0 = __ldg(h4 + (size_t)s0 * 32 + lane);
        float4 v1 = __ldg(h4 + (size_t)s1 * 32 + lane);
        float4 v2 = __ldg(h4 + (size_t)s2 * 32 + lane);
        float4 v3 = __ldg(h4 + (size_t)s3 * 32 + lane);
        acc.x += v0.x * n0 + v1.x * n1 + v2.x * n2 + v3.x * n3;
        acc.y += v0.y * n0 + v1.y * n1 + v2.y * n2 + v3.y * n3;
        acc.z += v0.z * n0 + v1.z * n1 + v2.z * n2 + v3.z * n3;
        acc.w += v0.w * n0 + v1.w * n1 + v2.w * n2 + v3.w * n3;
    }
    for (; e < end; ++e) {
        int s = __ldg(csr + e);
        float n = __ldg(norm + s);
        float4 v = __ldg(h4 + (size_t)s * 32 + lane);
        acc.x += v.x * n; acc.y += v.y * n; acc.z += v.z * n; acc.w += v.w * n;
    }
    float nd = __ldg(norm + warp);
    acc.x *= nd; acc.y *= nd; acc.z *= nd; acc.w *= nd;
    reinterpret_cast<float4*>(out)[(size_t)warp * 32 + lane] = acc;
}

__global__ __launch_bounds__(256)
void prop_pull32(const float* __restrict__ h, const float* __restrict__ norm,
                 const int* __restrict__ rowptr, const int* __restrict__ csr,
                 float* __restrict__ out, int N) {
    int t = blockIdx.x * blockDim.x + threadIdx.x;
    int node = t >> 3;
    int lane = t & 7;
    if (node >= N) return;
    int beg = __ldg(rowptr + node), end = __ldg(rowptr + node + 1);
    const float4* __restrict__ h4 = reinterpret_cast<const float4*>(h);
    float4 acc = make_float4(0.f, 0.f, 0.f, 0.f);
    int e = beg;
    for (; e + 4 <= end; e += 4) {
        int s0 = __ldg(csr + e), s1 = __ldg(csr + e + 1);
        int s2 = __ldg(csr + e + 2), s3 = __ldg(csr + e + 3);
        float n0 = __ldg(norm + s0), n1 = __ldg(norm + s1);
        float n2 = __ldg(norm + s2), n3 = __ldg(norm + s3);
        float4 v0 = __ldg(h4 + (size_t)s0 * 8 + lane);
        float4 v1 = __ldg(h4 + (size_t)s1 * 8 + lane);
        float4 v2 = __ldg(h4 + (size_t)s2 * 8 + lane);
        float4 v3 = __ldg(h4 + (size_t)s3 * 8 + lane);
        acc.x += v0.x * n0 + v1.x * n1 + v2.x * n2 + v3.x * n3;
        acc.y += v0.y * n0 + v1.y * n1 + v2.y * n2 + v3.y * n3;
        acc.z += v0.z * n0 + v1.z * n1 + v2.z * n2 + v3.z * n3;
        acc.w += v0.w * n0 + v1.w * n1 + v2.w * n2 + v3.w * n3;
    }
    for (; e < end; ++e) {
        int s = __ldg(csr + e);
        float n = __ldg(norm + s);
        float4 v = __ldg(h4 + (size_t)s * 8 + lane);
        acc.x += v.x * n; acc.y += v.y * n; acc.z += v.z * n; acc.w += v.w * n;
    }
    float nd = __ldg(norm + node);
    acc.x *= nd; acc.y *= nd; acc.z *= nd; acc.w *= nd;
    reinterpret_cast<float4*>(out)[(size_t)node * 8 + lane] = acc;
}

// ---------------------------------------------------------------------------
// TF32 tensor-core fused GEMM:
// out = relu(H0@W[0:DIN] + H1@W[DIN:2DIN] + H2@W[2DIN:3DIN] + b)
// BM=128, BN=128, BK=32, 256 threads = 8 warps, each warp owns 32x64 of C.
// ---------------------------------------------------------------------------
__device__ __forceinline__ uint32_t f2tf32(float f) {
    uint32_t u;
    asm("cvt.rna.tf32.f32 %0, %1;" : "=r"(u) : "f"(f));
    return u;
}

__device__ __forceinline__ void mma_tf32(float c[4], const uint32_t a[4], const uint32_t b[2]) {
    asm volatile(
        "mma.sync.aligned.m16n8k8.row.col.f32.tf32.tf32.f32 "
        "{%0,%1,%2,%3}, {%4,%5,%6,%7}, {%8,%9}, {%0,%1,%2,%3};"
        : "+f"(c[0]), "+f"(c[1]), "+f"(c[2]), "+f"(c[3])
        : "r"(a[0]), "r"(a[1]), "r"(a[2]), "r"(a[3]), "r"(b[0]), "r"(b[1]));
}

template <int DIN>
__global__ __launch_bounds__(256)
void gemm3_tf32(const float* __restrict__ H0, const float* __restrict__ H1,
                const float* __restrict__ H2, const float* __restrict__ W,
                const float* __restrict__ bias, float* __restrict__ out, int N) {
    __shared__ __align__(16) uint32_t As[32][132];   // As[k][m] (tf32 bits)
    __shared__ __align__(16) uint32_t Bs[32][128];   // Bs[k][n] (tf32 bits)

    const int tid     = threadIdx.x;
    const int wid     = tid >> 5;
    const int lane    = tid & 31;
    const int warp_m  = wid & 3;        // 4 warps along M: 32 rows each
    const int warp_n  = wid >> 2;       // 2 warps along N: 64 cols each
    const int groupID = lane >> 2;      // 0..7
    const int tig     = lane & 3;       // 0..3
    const int m0      = blockIdx.x * 128;

    float c[2][8][4];
#pragma unroll
    for (int mt = 0; mt < 2; mt++)
#pragma unroll
        for (int nt = 0; nt < 8; nt++)
#pragma unroll
            for (int i = 0; i < 4; i++) c[mt][nt][i] = 0.0f;

    const float* srcs[3] = {H0, H1, H2};

    const int aRow = tid >> 3;          // 0..31
    const int aCol = (tid & 7) * 4;     // 0..28
    const int bRow = tid >> 5;          // 0..7
    const int bCol = (tid & 31) * 4;    // 0..124

    for (int part = 0; part < 3; ++part) {
        const float* __restrict__ Hp = srcs[part];
        for (int k0 = 0; k0 < DIN; k0 += 32) {
            // A tile: 128 rows x 32 k, store transposed as tf32 bits
#pragma unroll
            for (int r = 0; r < 4; ++r) {
                int row = m0 + r * 32 + aRow;
                float4 v = make_float4(0.f, 0.f, 0.f, 0.f);
                if (row < N)
                    v = __ldg(reinterpret_cast<const float4*>(Hp + (size_t)row * DIN + k0 + aCol));
                As[aCol + 0][r * 32 + aRow] = f2tf32(v.x);
                As[aCol + 1][r * 32 + aRow] = f2tf32(v.y);
                As[aCol + 2][r * 32 + aRow] = f2tf32(v.z);
                As[aCol + 3][r * 32 + aRow] = f2tf32(v.w);
            }
            // B tile: 32 k-rows x 128 n
#pragma unroll
            for (int r = 0; r < 4; ++r) {
                int krow = r * 8 + bRow;
                float4 v = __ldg(reinterpret_cast<const float4*>(
                    W + (size_t)(part * DIN + k0 + krow) * 128 + bCol));
                uint4 u;
                u.x = f2tf32(v.x); u.y = f2tf32(v.y);
                u.z = f2tf32(v.z); u.w = f2tf32(v.w);
                *reinterpret_cast<uint4*>(&Bs[krow][bCol]) = u;
            }
            __syncthreads();

#pragma unroll
            for (int kk = 0; kk < 4; ++kk) {
                const int kb = kk * 8;
                uint32_t a[2][4];
#pragma unroll
                for (int mt = 0; mt < 2; mt++) {
                    int m = warp_m * 32 + mt * 16 + groupID;
                    a[mt][0] = As[kb + tig][m];
                    a[mt][1] = As[kb + tig][m + 8];
                    a[mt][2] = As[kb + tig + 4][m];
                    a[mt][3] = As[kb + tig + 4][m + 8];
                }
                uint32_t b[8][2];
#pragma unroll
                for (int nt = 0; nt < 8; nt++) {
                    int n = warp_n * 64 + nt * 8 + groupID;
                    b[nt][0] = Bs[kb + tig][n];
                    b[nt][1] = Bs[kb + tig + 4][n];
                }
#pragma unroll
                for (int mt = 0; mt < 2; mt++)
#pragma unroll
                    for (int nt = 0; nt < 8; nt++)
                        mma_tf32(c[mt][nt], a[mt], b[nt]);
            }
            __syncthreads();
        }
    }

    // epilogue: bias + relu, float2 stores
#pragma unroll
    for (int nt = 0; nt < 8; nt++) {
        int col = warp_n * 64 + nt * 8 + tig * 2;
        float2 bv = __ldg(reinterpret_cast<const float2*>(bias + col));
#pragma unroll
        for (int mt = 0; mt < 2; mt++) {
            int row0 = m0 + warp_m * 32 + mt * 16 + groupID;
            if (row0 < N) {
                float2 o;
                o.x = fmaxf(c[mt][nt][0] + bv.x, 0.f);
                o.y = fmaxf(c[mt][nt][1] + bv.y, 0.f);
                *reinterpret_cast<float2*>(out + (size_t)row0 * 128 + col) = o;
            }
            int row1 = row0 + 8;
            if (row1 < N) {
                float2 o;
                o.x = fmaxf(c[mt][nt][2] + bv.x, 0.f);
                o.y = fmaxf(c[mt][nt][3] + bv.y, 0.f);
                *reinterpret_cast<float2*>(out + (size_t)row1 * 128 + col) = o;
            }
        }
    }
}

// ---------------------------------------------------------------------------
// launch
// ---------------------------------------------------------------------------
extern "C" void kernel_launch(void* const* d_in, const int* in_sizes, int n_in,
                              void* d_out, int out_size) {
    const float* x   = (const float*)d_in[0];
    const int*   src = (const int*)d_in[1];
    const int*   dst = (const int*)d_in[2];
    const float* W1  = (const float*)d_in[3];
    const float* b1  = (const float*)d_in[4];
    const float* W2  = (const float*)d_in[5];
    const float* b2  = (const float*)d_in[6];
    const float* W3  = (const float*)d_in[7];
    const float* b3  = (const float*)d_in[8];
    float* out = (float*)d_out;

    const int N = in_sizes[0] / 32;
    const int E = in_sizes[1];

    float *p_norm, *p_t1, *p_t2, *p_h1, *p_h2;
    int *p_cnt, *p_rowptr, *p_cursor, *p_bsums, *p_csr;
    cudaGetSymbolAddress((void**)&p_norm,   g_norm);
    cudaGetSymbolAddress((void**)&p_cnt,    g_cnt);
    cudaGetSymbolAddress((void**)&p_rowptr, g_rowptr);
    cudaGetSymbolAddress((void**)&p_cursor, g_cursor);
    cudaGetSymbolAddress((void**)&p_bsums,  g_bsums);
    cudaGetSymbolAddress((void**)&p_csr,    g_csr);
    cudaGetSymbolAddress((void**)&p_t1,     g_t1);
    cudaGetSymbolAddress((void**)&p_t2,     g_t2);
    cudaGetSymbolAddress((void**)&p_h1,     g_h1);
    cudaGetSymbolAddress((void**)&p_h2,     g_h2);

    const int TB = 256;
    const int nb = (N + 1023) / 1024;

    // degree + norm
    cudaMemsetAsync(p_cnt, 0, (size_t)N * sizeof(int));
    hist_kernel<<<(E + TB - 1) / TB, TB>>>(dst, E, p_cnt);
    norm_kernel<<<(N + TB - 1) / TB, TB>>>(p_cnt, p_norm, N);

    // CSR build
    scan_block<<<nb, 256>>>(p_cnt, p_rowptr, p_bsums, N);
    scan_sums<<<1, 128>>>(p_bsums, nb);
    add_off<<<nb, 256>>>(p_rowptr, p_bsums, N, E);
    cudaMemcpyAsync(p_cursor, p_rowptr, (size_t)N * sizeof(int),
                    cudaMemcpyDeviceToDevice);
    scatter_kernel<<<(E + TB - 1) / TB, TB>>>(src, dst, E, p_cursor, p_csr);

    const int g128 = (N * 32 + TB - 1) / TB;   // warp per node
    const int g32  = (N * 8 + TB - 1) / TB;    // 8 lanes per node
    const int gg   = (N + 127) / 128;

    // ---- layer 1 (din = 32) ----
    prop_pull32<<<g32, TB>>>(x,    p_norm, p_rowptr, p_csr, p_t1, N);
    prop_pull32<<<g32, TB>>>(p_t1, p_norm, p_rowptr, p_csr, p_t2, N);
    gemm3_tf32<32><<<gg, 256>>>(x, p_t1, p_t2, W1, b1, p_h1, N);

    // ---- layer 2 (din = 128) ----
    prop_pull128<<<g128, TB>>>(p_h1, p_norm, p_rowptr, p_csr, p_t1, N);
    prop_pull128<<<g128, TB>>>(p_t1, p_norm, p_rowptr, p_csr, p_t2, N);
    gemm3_tf32<128><<<gg, 256>>>(p_h1, p_t1, p_t2, W2, b2, p_h2, N);

    // ---- layer 3 (din = 128) ----
    prop_pull128<<<g128, TB>>>(p_h2, p_norm, p_rowptr, p_csr, p_t1, N);
    prop_pull128<<<g128, TB>>>(p_t1, p_norm, p_rowptr, p_csr, p_t2, N);
    gemm3_tf32<128><<<gg, 256>>>(p_h2, p_t1, p_t2, W3, b3, out, N);
}